// round 4
// baseline (speedup 1.0000x reference)
#include <cuda_runtime.h>

#define BATCH 32
#define DIM   1024
#define INNER 2048
#define GRP   2                 // batches per pipeline group (L2-resident)
#define NGRP  (BATCH / GRP)     // 16

// ---------------- device scratch ----------------
__device__ __align__(16) float g_qkvpart[8 * BATCH * 4096];    // [dc][b][j]
__device__ __align__(16) float g_colpart[32 * BATCH * INNER];  // [z][b][j]
__device__ __align__(16) float g_kp[BATCH * INNER];
__device__ __align__(16) float g_qp[BATCH * INNER];
__device__ __align__(16) float g_vv[BATCH * INNER];
__device__ __align__(16) float g_beta[BATCH];
__device__ __align__(16) float g_outv[BATCH * INNER];
__device__ __align__(16) float g_opart[64 * BATCH * DIM];      // [ic][b][jo]

// ---------------- K1: qkv partial GEMM -------------------------------
__global__ void k_qkv(const float* __restrict__ x,
                      const float* __restrict__ Wq,
                      const float* __restrict__ Wk,
                      const float* __restrict__ Wv) {
    __shared__ __align__(16) float shx[32 * 128];
    const int jc = blockIdx.x & 15, dc = blockIdx.x >> 4, tid = threadIdx.x;
    for (int t = tid; t < 32 * 128; t += 256) {
        int b = t >> 7, dd = t & 127;
        shx[t] = x[b * DIM + dc * 128 + dd];
    }
    __syncthreads();

    const int j = jc * 256 + tid;  // 0..4095
    const float* Wm; int col, ncols;
    if (j < 1024)      { Wm = Wq; col = j;        ncols = 1024; }
    else if (j < 2048) { Wm = Wk; col = j - 1024; ncols = 1024; }
    else               { Wm = Wv; col = j - 2048; ncols = 2048; }

    float acc[32];
#pragma unroll
    for (int b = 0; b < 32; b++) acc[b] = 0.f;
    const float* wp = Wm + (size_t)(dc * 128) * ncols + col;
    for (int dd = 0; dd < 128; dd += 4) {
        float w0 = wp[(size_t)(dd + 0) * ncols];
        float w1 = wp[(size_t)(dd + 1) * ncols];
        float w2 = wp[(size_t)(dd + 2) * ncols];
        float w3 = wp[(size_t)(dd + 3) * ncols];
#pragma unroll
        for (int b = 0; b < 32; b++) {
            const float4 xv = *(const float4*)&shx[b * 128 + dd];
            acc[b] = fmaf(xv.x, w0, fmaf(xv.y, w1, fmaf(xv.z, w2, fmaf(xv.w, w3, acc[b]))));
        }
    }
#pragma unroll
    for (int b = 0; b < 32; b++)
        g_qkvpart[(size_t)(dc * 32 + b) * 4096 + j] = acc[b];
}

// ---------------- K2: beta, kp, qp, vv -------------------------------
__device__ __forceinline__ float sum8_qkv(int b, int j) {
    float s = 0.f;
#pragma unroll
    for (int dc = 0; dc < 8; dc++) s += g_qkvpart[(size_t)(dc * 32 + b) * 4096 + j];
    return s;
}

__device__ __forceinline__ float feat(int b, int j, int base, const float* __restrict__ bias) {
    const int c = j & 1023;
    float v = sum8_qkv(b, base + c) + bias[c];
    v = (j < 1024) ? v : -v;
    return fmaxf(v, 0.f);
}

__global__ void k_mid(const float* __restrict__ x,
                      const float* __restrict__ Wb,
                      const float* __restrict__ bb,
                      const float* __restrict__ bq,
                      const float* __restrict__ bk,
                      const float* __restrict__ bv) {
    const int b = blockIdx.y, jc = blockIdx.x, tid = threadIdx.x;

    float s = 0.f;
    for (int d = tid; d < DIM; d += 256) s += x[b * DIM + d] * Wb[d];
#pragma unroll
    for (int o = 16; o; o >>= 1) s += __shfl_down_sync(0xffffffffu, s, o);
    __shared__ float shr[8];
    if ((tid & 31) == 0) shr[tid >> 5] = s;
    __syncthreads();
    if (tid == 0 && jc == 0) {
        float t = 0.f;
#pragma unroll
        for (int u = 0; u < 8; u++) t += shr[u];
        t += bb[0];
        g_beta[b] = 1.f / (1.f + expf(-t));
    }

    const int j = jc * 256 + tid;
    const int jm = (j + INNER - 1) & (INNER - 1);
    g_kp[b * INNER + j] = feat(b, j, 1024, bk) * feat(b, jm, 1024, bk);
    g_qp[b * INNER + j] = feat(b, j, 0, bq) * feat(b, jm, 0, bq);
    g_vv[b * INNER + j] = sum8_qkv(b, 2048 + j) + bv[j];
}

// ---------------- K3: pipelined colsum(gc) + update(gu) --------------
// One launch = update of group gu (reads W from L2, resident from previous
// launch's colsum) + colsum of group gc (pulls next W slice from DRAM,
// leaving it L2-resident). gc/gu == -1 -> role idle.
// Grid: 512 update blocks + 64 colsum blocks = 576.
__global__ void k_pipe(const float* __restrict__ W, float* __restrict__ wnew,
                       int gc, int gu) {
    const int bid = blockIdx.x, tid = threadIdx.x;

    if (bid >= 512) {
        // ---------- colsum role: 64 blocks, 64 rows x 2048 cols each ----
        if (gc < 0) return;
        const int cb = bid - 512;
        const int b = gc * GRP + (cb >> 5);
        const int z = cb & 31;
        const size_t rowbase = ((size_t)b * INNER + z * 64) * INNER;
#pragma unroll
        for (int h = 0; h < 2; h++) {
            const int c = h * 1024 + tid * 4;
            const float4* p = (const float4*)(W + rowbase + c);
            float4 a0 = {0,0,0,0}, a1 = {0,0,0,0}, a2 = {0,0,0,0}, a3 = {0,0,0,0};
            for (int r = 0; r < 64; r += 4) {
                float4 v0 = __ldcg(&p[(size_t)(r + 0) * 512]);
                float4 v1 = __ldcg(&p[(size_t)(r + 1) * 512]);
                float4 v2 = __ldcg(&p[(size_t)(r + 2) * 512]);
                float4 v3 = __ldcg(&p[(size_t)(r + 3) * 512]);
                a0.x += v0.x; a0.y += v0.y; a0.z += v0.z; a0.w += v0.w;
                a1.x += v1.x; a1.y += v1.y; a1.z += v1.z; a1.w += v1.w;
                a2.x += v2.x; a2.y += v2.y; a2.z += v2.z; a2.w += v2.w;
                a3.x += v3.x; a3.y += v3.y; a3.z += v3.z; a3.w += v3.w;
            }
            float4 s;
            s.x = (a0.x + a1.x) + (a2.x + a3.x);
            s.y = (a0.y + a1.y) + (a2.y + a3.y);
            s.z = (a0.z + a1.z) + (a2.z + a3.z);
            s.w = (a0.w + a1.w) + (a2.w + a3.w);
            *(float4*)(g_colpart + ((size_t)z * BATCH + b) * INNER + c) = s;
        }
    } else {
        // ---------- update role: 512 blocks, 8 rows each ----------------
        if (gu < 0) return;
        const int b = gu * GRP + (bid >> 8);
        const int i0 = (bid & 255) * 8;
        __shared__ __align__(16) float4 shkp[512];
        const float4* kpv4 = (const float4*)(g_kp + b * INNER);
        for (int t = tid; t < 512; t += 256) shkp[t] = kpv4[t];
        __syncthreads();

        const int w = tid >> 5, lane = tid & 31;
        const int i = i0 + w;

        // dv[b][i]: colsum over 32 z-partials via lane-parallel read + shfl
        float cs = g_colpart[(size_t)lane * BATCH * INNER + (size_t)b * INNER + i];
#pragma unroll
        for (int o = 16; o; o >>= 1) cs += __shfl_down_sync(0xffffffffu, cs, o);
        cs = __shfl_sync(0xffffffffu, cs, 0);
        const float kpi = ((const float*)shkp)[i];
        const float dvi = g_beta[b] * (g_vv[b * INNER + i] - cs * kpi);

        const size_t base = ((size_t)b * INNER + i) * INNER;
        const float4* Wr = (const float4*)(W + base);
        float4* Or = (float4*)(wnew + base);

        float lsum = 0.f;
#pragma unroll
        for (int t = lane; t < 512; t += 32) {
            float4 wv = __ldcg(&Wr[t]);   // expect L2 hit (resident from prev launch)
            float4 kp4 = shkp[t];
            float4 r;
            r.x = fmaf(dvi, kp4.x, wv.x);
            r.y = fmaf(dvi, kp4.y, wv.y);
            r.z = fmaf(dvi, kp4.z, wv.z);
            r.w = fmaf(dvi, kp4.w, wv.w);
            __stcs(&Or[t], r);            // evict-first: protect resident W
            lsum += (r.x + r.y) + (r.z + r.w);
        }
#pragma unroll
        for (int o = 16; o; o >>= 1) lsum += __shfl_down_sync(0xffffffffu, lsum, o);
        if (lane == 0) g_outv[b * INNER + i] = lsum * g_qp[b * INNER + i];
    }
}

// ---------------- K4: out partials = outv @ Wo (256 CTAs) ------------
__global__ void k_outpart(const float* __restrict__ Wo) {
    __shared__ __align__(16) float sh[32 * 32];
    const int jc = blockIdx.x, ic = blockIdx.y, tid = threadIdx.x;
    for (int t = tid; t < 32 * 32; t += 256) {
        int b = t >> 5, ii = t & 31;
        sh[t] = g_outv[b * INNER + ic * 32 + ii];
    }
    __syncthreads();

    const int jo = jc * 256 + tid;
    float acc[32];
#pragma unroll
    for (int b = 0; b < 32; b++) acc[b] = 0.f;
    const float* wp = Wo + (size_t)(ic * 32) * DIM + jo;
#pragma unroll
    for (int ii = 0; ii < 32; ii += 4) {
        float w0 = wp[(size_t)(ii + 0) * DIM];
        float w1 = wp[(size_t)(ii + 1) * DIM];
        float w2 = wp[(size_t)(ii + 2) * DIM];
        float w3 = wp[(size_t)(ii + 3) * DIM];
#pragma unroll
        for (int b = 0; b < 32; b++) {
            const float4 xv = *(const float4*)&sh[b * 32 + ii];
            acc[b] = fmaf(xv.x, w0, fmaf(xv.y, w1, fmaf(xv.z, w2, fmaf(xv.w, w3, acc[b]))));
        }
    }
#pragma unroll
    for (int b = 0; b < 32; b++)
        g_opart[(size_t)(ic * 32 + b) * DIM + jo] = acc[b];
}

// ---------------- K5: out finalize -----------------------------------
__global__ void k_outfinal(const float* __restrict__ bo, float* __restrict__ out) {
    const int idx = blockIdx.x * 256 + threadIdx.x;  // 32768
    const int jo = idx & 1023, b = idx >> 10;
    float s = bo[jo];
#pragma unroll
    for (int ic = 0; ic < 64; ic++) s += g_opart[(size_t)(ic * 32 + b) * DIM + jo];
    out[idx] = s;
}

// ---------------- launch ---------------------------------------------
extern "C" void kernel_launch(void* const* d_in, const int* in_sizes, int n_in,
                              void* d_out, int out_size) {
    const float* x  = (const float*)d_in[0];
    const float* W  = (const float*)d_in[1];
    const float* Wq = (const float*)d_in[2];
    const float* bq = (const float*)d_in[3];
    const float* Wk = (const float*)d_in[4];
    const float* bk = (const float*)d_in[5];
    const float* Wv = (const float*)d_in[6];
    const float* bv = (const float*)d_in[7];
    const float* Wo = (const float*)d_in[8];
    const float* bo = (const float*)d_in[9];
    const float* Wb = (const float*)d_in[10];
    const float* bb = (const float*)d_in[11];

    float* out  = (float*)d_out;
    float* wnew = out + BATCH * DIM;

    k_qkv<<<128, 256>>>(x, Wq, Wk, Wv);
    k_mid<<<dim3(8, 32), 256>>>(x, Wb, bb, bq, bk, bv);
    // Software-pipelined: launch g does colsum(g) + update(g-1).
    for (int g = 0; g <= NGRP; g++) {
        const int gc = (g < NGRP) ? g : -1;
        const int gu = g - 1;
        k_pipe<<<576, 256>>>(W, wnew, gc, gu);
    }
    k_outpart <<<dim3(4, 64), 256>>>(Wo);
    k_outfinal<<<128,         256>>>(bo, out);
}

// round 8
// speedup vs baseline: 1.0485x; 1.0485x over previous
#include <cuda_runtime.h>

#define BATCH 32
#define DIM   1024
#define INNER 2048
#define NBLK  296              // 2 blocks/SM x 148 SMs, co-resident by launch_bounds
#define ZLEV  148              // colsum row-split levels
#define ZPAD  152              // padded z stride
#define CPB   (INNER * ZPAD)   // floats per colpart buffer

// ---------------- device scratch ----------------
__device__ unsigned g_bar;
__device__ __align__(16) float g_qkvpart[8 * BATCH * 4096];
__device__ __align__(16) float g_colpart[4 * CPB];           // 4 ring buffers
__device__ __align__(16) float g_kp[BATCH * INNER];
__device__ __align__(16) float g_qp[BATCH * INNER];
__device__ __align__(16) float g_vv[BATCH * INNER];
__device__ __align__(16) float g_beta[BATCH];
__device__ __align__(16) float g_outv[BATCH * INNER];
__device__ __align__(16) float g_opart[64 * BATCH * DIM];

__global__ void k_init() { g_bar = 0; }

// ---- grid-wide barrier (all NBLK blocks co-resident) ----
__device__ __forceinline__ void gsync(unsigned& epoch) {
    __syncthreads();
    if (threadIdx.x == 0) {
        epoch += NBLK;
        __threadfence();
        atomicAdd(&g_bar, 1u);
        while (*(volatile unsigned*)&g_bar < epoch) __nanosleep(64);
        __threadfence();
    }
    __syncthreads();
}

// ---- colsum slice of batch bc: block (z,h), up to 14 rows x 1024 cols ----
__device__ __forceinline__ void colsum_work(const float* __restrict__ W,
                                            int bc, int bid, int tid) {
    const int z = bid >> 1, h = bid & 1;
    const int r0 = z * 14;
    if (r0 >= INNER) return;
    const int r1 = (r0 + 14 < INNER) ? r0 + 14 : INNER;
    const int c = h * 1024 + tid * 4;
    const float* p = W + ((size_t)bc * INNER + r0) * INNER + c;
    float4 a0 = {0,0,0,0}, a1 = {0,0,0,0}, a2 = {0,0,0,0}, a3 = {0,0,0,0};
    int r = r0;
    for (; r + 4 <= r1; r += 4) {
        float4 v0 = __ldcg((const float4*)(p + 0 * INNER));
        float4 v1 = __ldcg((const float4*)(p + 1 * INNER));
        float4 v2 = __ldcg((const float4*)(p + 2 * INNER));
        float4 v3 = __ldcg((const float4*)(p + 3 * INNER));
        a0.x += v0.x; a0.y += v0.y; a0.z += v0.z; a0.w += v0.w;
        a1.x += v1.x; a1.y += v1.y; a1.z += v1.z; a1.w += v1.w;
        a2.x += v2.x; a2.y += v2.y; a2.z += v2.z; a2.w += v2.w;
        a3.x += v3.x; a3.y += v3.y; a3.z += v3.z; a3.w += v3.w;
        p += (size_t)4 * INNER;
    }
    for (; r < r1; ++r) {
        float4 v = __ldcg((const float4*)p);
        a0.x += v.x; a0.y += v.y; a0.z += v.z; a0.w += v.w;
        p += INNER;
    }
    float4 s;
    s.x = (a0.x + a1.x) + (a2.x + a3.x);
    s.y = (a0.y + a1.y) + (a2.y + a3.y);
    s.z = (a0.z + a1.z) + (a2.z + a3.z);
    s.w = (a0.w + a1.w) + (a2.w + a3.w);
    float* cp = g_colpart + (size_t)(bc & 3) * CPB;
    cp[(size_t)(c + 0) * ZPAD + z] = s.x;
    cp[(size_t)(c + 1) * ZPAD + z] = s.y;
    cp[(size_t)(c + 2) * ZPAD + z] = s.z;
    cp[(size_t)(c + 3) * ZPAD + z] = s.w;
}

// ---- qkv partial GEMM (blocks 0..127) ----
__device__ __forceinline__ void qkv_work(const float* __restrict__ x,
                                         const float* __restrict__ Wq,
                                         const float* __restrict__ Wk,
                                         const float* __restrict__ Wv,
                                         int bid, int tid, float* smem) {
    const int jc = bid & 15, dc = bid >> 4;
    for (int t = tid; t < 32 * 128; t += 256) {
        int b = t >> 7, dd = t & 127;
        smem[t] = x[b * DIM + dc * 128 + dd];
    }
    __syncthreads();
    const int j = jc * 256 + tid;
    const float* Wm; int col, ncols;
    if (j < 1024)      { Wm = Wq; col = j;        ncols = 1024; }
    else if (j < 2048) { Wm = Wk; col = j - 1024; ncols = 1024; }
    else               { Wm = Wv; col = j - 2048; ncols = 2048; }
    float acc[32];
#pragma unroll
    for (int b = 0; b < 32; b++) acc[b] = 0.f;
    const float* wp = Wm + (size_t)(dc * 128) * ncols + col;
    for (int dd = 0; dd < 128; dd += 4) {
        float w0 = wp[(size_t)(dd + 0) * ncols];
        float w1 = wp[(size_t)(dd + 1) * ncols];
        float w2 = wp[(size_t)(dd + 2) * ncols];
        float w3 = wp[(size_t)(dd + 3) * ncols];
#pragma unroll
        for (int b = 0; b < 32; b++) {
            const float4 xv = *(const float4*)&smem[b * 128 + dd];
            acc[b] = fmaf(xv.x, w0, fmaf(xv.y, w1, fmaf(xv.z, w2, fmaf(xv.w, w3, acc[b]))));
        }
    }
#pragma unroll
    for (int b = 0; b < 32; b++)
        g_qkvpart[(size_t)(dc * 32 + b) * 4096 + j] = acc[b];
}

// ---- mid: beta, kp, qp, vv (blocks 0..255) ----
__device__ __forceinline__ float sum8_qkv(int b, int j) {
    float s = 0.f;
#pragma unroll
    for (int dc = 0; dc < 8; dc++) s += g_qkvpart[(size_t)(dc * 32 + b) * 4096 + j];
    return s;
}
__device__ __forceinline__ float feat(int b, int j, int base, const float* __restrict__ bias) {
    const int c = j & 1023;
    float v = sum8_qkv(b, base + c) + bias[c];
    v = (j < 1024) ? v : -v;
    return fmaxf(v, 0.f);
}
__device__ __forceinline__ void mid_work(const float* __restrict__ x,
                                         const float* __restrict__ Wb,
                                         const float* __restrict__ bb,
                                         const float* __restrict__ bq,
                                         const float* __restrict__ bk,
                                         const float* __restrict__ bv,
                                         int bid, int tid, float* smem) {
    const int jc = bid & 7, b = bid >> 3;
    float s = 0.f;
    for (int d = tid; d < DIM; d += 256) s += x[b * DIM + d] * Wb[d];
#pragma unroll
    for (int o = 16; o; o >>= 1) s += __shfl_down_sync(0xffffffffu, s, o);
    if ((tid & 31) == 0) smem[tid >> 5] = s;
    __syncthreads();
    if (tid == 0 && jc == 0) {
        float t = 0.f;
#pragma unroll
        for (int u = 0; u < 8; u++) t += smem[u];
        t += bb[0];
        g_beta[b] = 1.f / (1.f + expf(-t));
    }
    const int j = jc * 256 + tid;
    const int jm = (j + INNER - 1) & (INNER - 1);
    g_kp[b * INNER + j] = feat(b, j, 1024, bk) * feat(b, jm, 1024, bk);
    g_qp[b * INNER + j] = feat(b, j, 0, bq) * feat(b, jm, 0, bq);
    g_vv[b * INNER + j] = sum8_qkv(b, 2048 + j) + bv[j];
}

// ---- update batch bu: each block 6-7 rows, warp per row, W reads hit L2 ----
__device__ __forceinline__ void update_work(const float* __restrict__ W,
                                            float* __restrict__ wnew,
                                            int bu, int bid, int tid, float* smem) {
    const int r0 = (bid * INNER) / NBLK;
    const int r1 = ((bid + 1) * INNER) / NBLK;
    float4* sh4 = (float4*)smem;
    const float4* kpv4 = (const float4*)(g_kp + bu * INNER);
    for (int t = tid; t < 512; t += 256) sh4[t] = kpv4[t];
    __syncthreads();

    const int w = tid >> 5, lane = tid & 31;
    const int i = r0 + w;
    if (i < r1) {
        const float* cp = g_colpart + (size_t)(bu & 3) * CPB + (size_t)i * ZPAD;
        float cs = 0.f;
        for (int z = lane; z < ZLEV; z += 32) cs += cp[z];
#pragma unroll
        for (int o = 16; o; o >>= 1) cs += __shfl_xor_sync(0xffffffffu, cs, o);
        const float dvi = g_beta[bu] * (g_vv[bu * INNER + i] - cs * smem[i]);

        const size_t base = ((size_t)bu * INNER + i) * INNER;
        const float4* Wr = (const float4*)(W + base);
        float4* Or = (float4*)(wnew + base);
        float lsum = 0.f;
#pragma unroll 4
        for (int t = lane; t < 512; t += 32) {
            float4 wv = __ldcg(&Wr[t]);    // expect L2 hit (colsum 2 steps ago)
            float4 kp4 = sh4[t];
            float4 r;
            r.x = fmaf(dvi, kp4.x, wv.x);
            r.y = fmaf(dvi, kp4.y, wv.y);
            r.z = fmaf(dvi, kp4.z, wv.z);
            r.w = fmaf(dvi, kp4.w, wv.w);
            __stcs(&Or[t], r);             // evict-first: protect resident W
            lsum += (r.x + r.y) + (r.z + r.w);
        }
#pragma unroll
        for (int o = 16; o; o >>= 1) lsum += __shfl_down_sync(0xffffffffu, lsum, o);
        if (lane == 0) g_outv[bu * INNER + i] = lsum * g_qp[bu * INNER + i];
    }
}

// ---- outpart (blocks 0..255) + outfinal (blocks 0..127) ----
__device__ __forceinline__ void outpart_work(const float* __restrict__ Wo,
                                             int bid, int tid, float* smem) {
    const int jc = bid & 3, ic = bid >> 2;
    for (int t = tid; t < 32 * 32; t += 256) {
        int b = t >> 5, ii = t & 31;
        smem[t] = g_outv[b * INNER + ic * 32 + ii];
    }
    __syncthreads();
    const int jo = jc * 256 + tid;
    float acc[32];
#pragma unroll
    for (int b = 0; b < 32; b++) acc[b] = 0.f;
    const float* wp = Wo + (size_t)(ic * 32) * DIM + jo;
#pragma unroll
    for (int ii = 0; ii < 32; ii += 4) {
        float w0 = wp[(size_t)(ii + 0) * DIM];
        float w1 = wp[(size_t)(ii + 1) * DIM];
        float w2 = wp[(size_t)(ii + 2) * DIM];
        float w3 = wp[(size_t)(ii + 3) * DIM];
#pragma unroll
        for (int b = 0; b < 32; b++) {
            const float4 xv = *(const float4*)&smem[b * 32 + ii];
            acc[b] = fmaf(xv.x, w0, fmaf(xv.y, w1, fmaf(xv.z, w2, fmaf(xv.w, w3, acc[b]))));
        }
    }
#pragma unroll
    for (int b = 0; b < 32; b++)
        g_opart[(size_t)(ic * 32 + b) * DIM + jo] = acc[b];
}

__device__ __forceinline__ void outfinal_work(const float* __restrict__ bo,
                                              float* __restrict__ out,
                                              int bid, int tid) {
    const int idx = bid * 256 + tid;
    const int jo = idx & 1023, b = idx >> 10;
    float s = bo[jo];
#pragma unroll
    for (int ic = 0; ic < 64; ic++) s += g_opart[(size_t)(ic * 32 + b) * DIM + jo];
    out[idx] = s;
}

// ---------------- the persistent kernel ------------------------------
__global__ __launch_bounds__(256, 2) void k_main(
    const float* __restrict__ x,  const float* __restrict__ W,
    const float* __restrict__ Wq, const float* __restrict__ bq,
    const float* __restrict__ Wk, const float* __restrict__ bk,
    const float* __restrict__ Wv, const float* __restrict__ bv,
    const float* __restrict__ Wo, const float* __restrict__ bo,
    const float* __restrict__ Wb, const float* __restrict__ bb,
    float* __restrict__ out, float* __restrict__ wnew)
{
    __shared__ __align__(16) float smem[4096];
    unsigned epoch = 0;
    const int bid = blockIdx.x, tid = threadIdx.x;

    // s=0: qkv partials || colsum(0)
    if (bid < 128) qkv_work(x, Wq, Wk, Wv, bid, tid, smem);
    colsum_work(W, 0, bid, tid);
    gsync(epoch);

    // s=1: mid || colsum(1)
    if (bid < 256) mid_work(x, Wb, bb, bq, bk, bv, bid, tid, smem);
    colsum_work(W, 1, bid, tid);
    gsync(epoch);

    // s=2..33: update(s-2) || colsum(s)
    for (int s = 2; s <= 33; ++s) {
        update_work(W, wnew, s - 2, bid, tid, smem);
        if (s <= 31) colsum_work(W, s, bid, tid);
        gsync(epoch);
    }

    if (bid < 256) outpart_work(Wo, bid, tid, smem);
    gsync(epoch);
    if (bid < 128) outfinal_work(bo, out, bid, tid);
}

// ---------------- launch ---------------------------------------------
extern "C" void kernel_launch(void* const* d_in, const int* in_sizes, int n_in,
                              void* d_out, int out_size) {
    const float* x  = (const float*)d_in[0];
    const float* W  = (const float*)d_in[1];
    const float* Wq = (const float*)d_in[2];
    const float* bq = (const float*)d_in[3];
    const float* Wk = (const float*)d_in[4];
    const float* bk = (const float*)d_in[5];
    const float* Wv = (const float*)d_in[6];
    const float* bv = (const float*)d_in[7];
    const float* Wo = (const float*)d_in[8];
    const float* bo = (const float*)d_in[9];
    const float* Wb = (const float*)d_in[10];
    const float* bb = (const float*)d_in[11];

    float* out  = (float*)d_out;
    float* wnew = out + BATCH * DIM;

    k_init<<<1, 1>>>();
    k_main<<<NBLK, 256>>>(x, W, Wq, bq, Wk, bk, Wv, bv, Wo, bo, Wb, bb, out, wnew);
}

// round 9
// speedup vs baseline: 1.2738x; 1.2149x over previous
#include <cuda_runtime.h>

#define BATCH 32
#define DIM   1024
#define INNER 2048
#define NBLK  592              // pipe grid: one wave at ~4 CTAs/SM
#define ZLEV  74               // colsum row-split levels (2048/74 ~ 27.7 rows)

// ---------------- device scratch ----------------
__device__ __align__(16) float g_qkvpart[16 * BATCH * 4096];   // [dc][b][j]
__device__ __align__(16) float g_colpart[4 * ZLEV * INNER];    // [(g&1)*2+(b&1)][z][j]
__device__ __align__(16) float g_kp[BATCH * INNER];
__device__ __align__(16) float g_qp[BATCH * INNER];
__device__ __align__(16) float g_vv[BATCH * INNER];
__device__ __align__(16) float g_beta[BATCH];
__device__ __align__(16) float g_outv[BATCH * INNER];
__device__ __align__(16) float g_opart[64 * BATCH * DIM];      // [ic][b][jo]

// ---------------- K1: qkv partial GEMM (256 blocks) ------------------
__global__ __launch_bounds__(256) void k_qkv(const float* __restrict__ x,
                                             const float* __restrict__ Wq,
                                             const float* __restrict__ Wk,
                                             const float* __restrict__ Wv) {
    __shared__ __align__(16) float shx[32 * 64];
    const int jc = blockIdx.x & 15, dc = blockIdx.x >> 4, tid = threadIdx.x;
    for (int t = tid; t < 32 * 64; t += 256) {
        int b = t >> 6, dd = t & 63;
        shx[t] = x[b * DIM + dc * 64 + dd];
    }
    __syncthreads();

    const int j = jc * 256 + tid;  // 0..4095
    const float* Wm; int col, ncols;
    if (j < 1024)      { Wm = Wq; col = j;        ncols = 1024; }
    else if (j < 2048) { Wm = Wk; col = j - 1024; ncols = 1024; }
    else               { Wm = Wv; col = j - 2048; ncols = 2048; }

    float acc[32];
#pragma unroll
    for (int b = 0; b < 32; b++) acc[b] = 0.f;
    const float* wp = Wm + (size_t)(dc * 64) * ncols + col;
    for (int dd = 0; dd < 64; dd += 4) {
        float w0 = wp[(size_t)(dd + 0) * ncols];
        float w1 = wp[(size_t)(dd + 1) * ncols];
        float w2 = wp[(size_t)(dd + 2) * ncols];
        float w3 = wp[(size_t)(dd + 3) * ncols];
#pragma unroll
        for (int b = 0; b < 32; b++) {
            const float4 xv = *(const float4*)&shx[b * 64 + dd];
            acc[b] = fmaf(xv.x, w0, fmaf(xv.y, w1, fmaf(xv.z, w2, fmaf(xv.w, w3, acc[b]))));
        }
    }
#pragma unroll
    for (int b = 0; b < 32; b++)
        g_qkvpart[(size_t)(dc * 32 + b) * 4096 + j] = acc[b];
}

// ---------------- mid helpers ----------------------------------------
__device__ __forceinline__ float sum16_qkv(int b, int j) {
    float s = 0.f;
#pragma unroll
    for (int dc = 0; dc < 16; dc++) s += g_qkvpart[(size_t)(dc * 32 + b) * 4096 + j];
    return s;
}
__device__ __forceinline__ float feat(int b, int j, int base, const float* __restrict__ bias) {
    const int c = j & 1023;
    float v = sum16_qkv(b, base + c) + bias[c];
    v = (j < 1024) ? v : -v;
    return fmaxf(v, 0.f);
}
__device__ __forceinline__ void mid_work(const float* __restrict__ x,
                                         const float* __restrict__ Wb,
                                         const float* __restrict__ bb,
                                         const float* __restrict__ bq,
                                         const float* __restrict__ bk,
                                         const float* __restrict__ bv,
                                         int bid, int tid, float* smem) {
    const int jc = bid & 7, b = bid >> 3;
    float s = 0.f;
    for (int d = tid; d < DIM; d += 256) s += x[b * DIM + d] * Wb[d];
#pragma unroll
    for (int o = 16; o; o >>= 1) s += __shfl_down_sync(0xffffffffu, s, o);
    if ((tid & 31) == 0) smem[tid >> 5] = s;
    __syncthreads();
    if (tid == 0 && jc == 0) {
        float t = 0.f;
#pragma unroll
        for (int u = 0; u < 8; u++) t += smem[u];
        t += bb[0];
        g_beta[b] = 1.f / (1.f + expf(-t));
    }
    const int j = jc * 256 + tid;
    const int jm = (j + INNER - 1) & (INNER - 1);
    g_kp[b * INNER + j] = feat(b, j, 1024, bk) * feat(b, jm, 1024, bk);
    g_qp[b * INNER + j] = feat(b, j, 0, bq) * feat(b, jm, 0, bq);
    g_vv[b * INNER + j] = sum16_qkv(b, 2048 + j) + bv[j];
    __syncthreads();
}

// ---------------- K2: pipe = colsum(gc) + update(gu), balanced -------
// All NBLK blocks share both roles evenly. Lag-1 software pipeline:
// update(gu) reads W_gu from L2 (loaded by colsum in the previous launch).
__global__ __launch_bounds__(256) void k_pipe(
    const float* __restrict__ W, float* __restrict__ wnew,
    const float* __restrict__ x,  const float* __restrict__ Wb,
    const float* __restrict__ bb, const float* __restrict__ bq,
    const float* __restrict__ bk, const float* __restrict__ bv,
    int gc, int gu, int domid)
{
    __shared__ __align__(16) float smem[INNER];   // kp for update batch (8KB)
    const int bid = blockIdx.x, tid = threadIdx.x;

    if (domid && bid < 256) mid_work(x, Wb, bb, bq, bk, bv, bid, tid, smem);

    // ---- colsum role: 2 slices per block, column-per-thread ----
    if (gc >= 0) {
#pragma unroll
        for (int h = 0; h < 2; h++) {
            const int batch = gc * 2 + h;
            const int sl = bid;                 // 0..591 per batch
            const int cch = sl & 7, zc = sl >> 3;
            const int r0 = (zc * INNER) / ZLEV;
            const int r1 = ((zc + 1) * INNER) / ZLEV;
            const int col = cch * 256 + tid;
            const float* p = W + ((size_t)batch * INNER + r0) * INNER + col;
            float a0 = 0.f, a1 = 0.f, a2 = 0.f, a3 = 0.f;
            int r = r0;
            for (; r + 4 <= r1; r += 4) {
                a0 += __ldcg(p);
                a1 += __ldcg(p + INNER);
                a2 += __ldcg(p + 2 * INNER);
                a3 += __ldcg(p + 3 * INNER);
                p += (size_t)4 * INNER;
            }
            for (; r < r1; ++r) { a0 += __ldcg(p); p += INNER; }
            g_colpart[(size_t)(((gc & 1) * 2 + h) * ZLEV + zc) * INNER + col] =
                (a0 + a1) + (a2 + a3);
        }
    }

    // ---- update role: ~7 rows per block, warp-per-row ----
    if (gu >= 0) {
        const int half = (bid >= 296) ? 1 : 0;
        const int batch = gu * 2 + half;
        const int lb = bid - half * 296;        // 0..295 within batch
        const int r0 = (lb * INNER) / 296;
        const int r1 = ((lb + 1) * INNER) / 296;

        for (int t = tid; t < INNER; t += 256) smem[t] = g_kp[batch * INNER + t];
        __syncthreads();

        const int wid = tid >> 5, lane = tid & 31;
        const float beta = g_beta[batch];
        const float* cpb = g_colpart + (size_t)((gu & 1) * 2 + half) * ZLEV * INNER;

        for (int i = r0 + wid; i < r1; i += 8) {
            // cs = full column sum over ZLEV partials
            float cs = 0.f;
            for (int z = lane; z < ZLEV; z += 32) cs += cpb[(size_t)z * INNER + i];
#pragma unroll
            for (int o = 16; o; o >>= 1) cs += __shfl_xor_sync(0xffffffffu, cs, o);
            const float dvi = beta * (g_vv[batch * INNER + i] - cs * smem[i]);

            const size_t base = ((size_t)batch * INNER + i) * INNER;
            const float4* Wr = (const float4*)(W + base);
            float4* Or = (float4*)(wnew + base);
            const float4* kp4 = (const float4*)smem;
            float lsum = 0.f;
#pragma unroll 4
            for (int t = lane; t < 512; t += 32) {
                float4 wv = __ldcg(&Wr[t]);     // expect L2 hit (prev launch)
                float4 k4 = kp4[t];
                float4 r;
                r.x = fmaf(dvi, k4.x, wv.x);
                r.y = fmaf(dvi, k4.y, wv.y);
                r.z = fmaf(dvi, k4.z, wv.z);
                r.w = fmaf(dvi, k4.w, wv.w);
                __stcs(&Or[t], r);              // evict-first: protect resident W
                lsum += (r.x + r.y) + (r.z + r.w);
            }
#pragma unroll
            for (int o = 16; o; o >>= 1) lsum += __shfl_down_sync(0xffffffffu, lsum, o);
            if (lane == 0)
                g_outv[batch * INNER + i] = lsum * g_qp[batch * INNER + i];
        }
    }
}

// ---------------- K3: out partials = outv @ Wo (256 CTAs) ------------
__global__ __launch_bounds__(256) void k_outpart(const float* __restrict__ Wo) {
    __shared__ __align__(16) float sh[32 * 32];
    const int jc = blockIdx.x, ic = blockIdx.y, tid = threadIdx.x;
    for (int t = tid; t < 32 * 32; t += 256) {
        int b = t >> 5, ii = t & 31;
        sh[t] = g_outv[b * INNER + ic * 32 + ii];
    }
    __syncthreads();

    const int jo = jc * 256 + tid;
    float acc[32];
#pragma unroll
    for (int b = 0; b < 32; b++) acc[b] = 0.f;
    const float* wp = Wo + (size_t)(ic * 32) * DIM + jo;
#pragma unroll
    for (int ii = 0; ii < 32; ii += 4) {
        float w0 = wp[(size_t)(ii + 0) * DIM];
        float w1 = wp[(size_t)(ii + 1) * DIM];
        float w2 = wp[(size_t)(ii + 2) * DIM];
        float w3 = wp[(size_t)(ii + 3) * DIM];
#pragma unroll
        for (int b = 0; b < 32; b++) {
            const float4 xv = *(const float4*)&sh[b * 32 + ii];
            acc[b] = fmaf(xv.x, w0, fmaf(xv.y, w1, fmaf(xv.z, w2, fmaf(xv.w, w3, acc[b]))));
        }
    }
#pragma unroll
    for (int b = 0; b < 32; b++)
        g_opart[(size_t)(ic * 32 + b) * DIM + jo] = acc[b];
}

// ---------------- K4: out finalize -----------------------------------
__global__ __launch_bounds__(256) void k_outfinal(const float* __restrict__ bo,
                                                  float* __restrict__ out) {
    const int idx = blockIdx.x * 256 + threadIdx.x;  // 32768
    const int jo = idx & 1023, b = idx >> 10;
    float s = bo[jo];
#pragma unroll
    for (int ic = 0; ic < 64; ic++) s += g_opart[(size_t)(ic * 32 + b) * DIM + jo];
    out[idx] = s;
}

// ---------------- launch ---------------------------------------------
extern "C" void kernel_launch(void* const* d_in, const int* in_sizes, int n_in,
                              void* d_out, int out_size) {
    const float* x  = (const float*)d_in[0];
    const float* W  = (const float*)d_in[1];
    const float* Wq = (const float*)d_in[2];
    const float* bq = (const float*)d_in[3];
    const float* Wk = (const float*)d_in[4];
    const float* bk = (const float*)d_in[5];
    const float* Wv = (const float*)d_in[6];
    const float* bv = (const float*)d_in[7];
    const float* Wo = (const float*)d_in[8];
    const float* bo = (const float*)d_in[9];
    const float* Wb = (const float*)d_in[10];
    const float* bb = (const float*)d_in[11];

    float* out  = (float*)d_out;
    float* wnew = out + BATCH * DIM;

    k_qkv<<<256, 256>>>(x, Wq, Wk, Wv);
    // Lag-1 pipeline over 16 groups of 2 batches:
    //   pipe g: colsum(group g) [+ mid at g=0] + update(group g-1)
    for (int g = 0; g <= 16; g++) {
        const int gc = (g < 16) ? g : -1;
        const int gu = g - 1;
        k_pipe<<<NBLK, 256>>>(W, wnew, x, Wb, bb, bq, bk, bv, gc, gu, g == 0 ? 1 : 0);
    }
    k_outpart <<<dim3(4, 64), 256>>>(Wo);
    k_outfinal<<<128,         256>>>(bo, out);
}